// round 13
// baseline (speedup 1.0000x reference)
#include <cuda_runtime.h>
#include <cstdint>

// Problem constants (fixed by setup_inputs)
#define Bb   8
#define Nn   4096
#define Ee   16384
#define Pp   64
#define Dd   256
#define Hh   512
#define MSGm 256
#define UPDu 254
#define STEPS 3

#define SKA  20    // A smem row stride (words)
#define SKB  136   // B smem row stride (words)

// Scratch (device globals per harness allocation rules)
__device__ __align__(128) float g_ns  [(size_t)Bb * Nn * Dd];    // exact state
__device__ __align__(128) float g_nsr [(size_t)Bb * Nn * Dd];    // tf32-rounded state
__device__ __align__(128) float g_p   [(size_t)Bb * Nn * 1024];  // P = nsr @ [We1_top|We1_bot]
__device__ __align__(128) float g_msg [(size_t)Bb * Ee * MSGm];  // per-edge messages (+be2)
__device__ __align__(128) float g_inc [(size_t)Bb * Nn * MSGm];  // gathered messages (rounded)
__device__ __align__(128) float g_h2  [(size_t)Bb * Nn * Hh];    // rounded node hidden
__device__ __align__(128) float g_We1c[(size_t)Dd * 1024];       // combined+rounded W_e1
__device__ __align__(128) float g_We2r[(size_t)Hh * MSGm];
__device__ __align__(128) float g_Wn1r[(size_t)(Dd+MSGm) * Hh];
__device__ __align__(128) float g_Wn2r[(size_t)Hh * 256];        // padded 254 -> 256

// CSR of edge_sinks (static across steps; rebuilt each launch)
__device__ int g_cnt[Nn];
__device__ int g_off[Nn + 1];
__device__ int g_pos[Nn];
__device__ int g_eid[Ee];

// ---------------------------------------------------------------------------
__device__ __forceinline__ uint32_t f2tf(float x) {
    uint32_t u;
    asm("cvt.rna.tf32.f32 %0, %1;" : "=r"(u) : "f"(x));
    return u;
}
__device__ __forceinline__ float rndf(float x) { return __uint_as_float(f2tf(x)); }

__device__ __forceinline__ void mma8(float* c, uint32_t a0, uint32_t a1,
                                     uint32_t a2, uint32_t a3,
                                     uint32_t b0, uint32_t b1) {
    asm volatile(
        "mma.sync.aligned.m16n8k8.row.col.f32.tf32.tf32.f32 "
        "{%0,%1,%2,%3}, {%4,%5,%6,%7}, {%8,%9}, {%0,%1,%2,%3};"
        : "+f"(c[0]), "+f"(c[1]), "+f"(c[2]), "+f"(c[3])
        : "r"(a0), "r"(a1), "r"(a2), "r"(a3), "r"(b0), "r"(b1));
}

__device__ __forceinline__ void ldsm4(uint32_t& r0, uint32_t& r1,
                                      uint32_t& r2, uint32_t& r3, uint32_t addr) {
    asm volatile("ldmatrix.sync.aligned.m8n8.x4.shared.b16 {%0,%1,%2,%3}, [%4];"
                 : "=r"(r0), "=r"(r1), "=r"(r2), "=r"(r3) : "r"(addr));
}

__device__ __forceinline__ void cpa16(uint32_t dst, const float* src) {
    asm volatile("cp.async.ca.shared.global [%0], [%1], 16;"
                 :: "r"(dst), "l"(src));
}
#define CP_COMMIT asm volatile("cp.async.commit_group;")
#define CP_WAIT1  asm volatile("cp.async.wait_group 1;")
#define CP_WAIT0  asm volatile("cp.async.wait_group 0;")

// ---------------------------------------------------------------------------
// Prologue / utility kernels
__global__ void k_round(const float* __restrict__ src, float* __restrict__ dst, int n) {
    int i = blockIdx.x * blockDim.x + threadIdx.x;
    if (i < n) dst[i] = rndf(src[i]);
}

__global__ void k_make_we1c(const float* __restrict__ We1) {
    int i = blockIdx.x * blockDim.x + threadIdx.x;   // over Dd*1024
    if (i < Dd * 1024) {
        int k = i >> 10, j = i & 1023;
        float v = (j < Hh) ? We1[k * Hh + j] : We1[(Dd + k) * Hh + (j - Hh)];
        g_We1c[i] = rndf(v);
    }
}

__global__ void k_round_pad_wn2(const float* __restrict__ src) {
    int i = blockIdx.x * blockDim.x + threadIdx.x;   // over Hh*256
    if (i < Hh * 256) {
        int r = i >> 8, c = i & 255;
        g_Wn2r[i] = (c < UPDu) ? rndf(src[r * UPDu + c]) : 0.f;
    }
}

__global__ void k_copy_ns(const float* __restrict__ src) {
    size_t i = (size_t)blockIdx.x * blockDim.x + threadIdx.x;
    if (i < (size_t)Bb * Nn * Dd) {
        float v = src[i];
        g_ns[i]  = v;
        g_nsr[i] = rndf(v);
    }
}

// ---- CSR build (per launch; graph-captured) ----
__global__ void k_zero_csr() {
    int i = blockIdx.x * blockDim.x + threadIdx.x;
    if (i < Nn) { g_cnt[i] = 0; g_pos[i] = 0; }
}

__global__ void k_hist(const int* __restrict__ esnk) {
    int e = blockIdx.x * blockDim.x + threadIdx.x;
    if (e < Ee) atomicAdd(&g_cnt[esnk[e]], 1);
}

__global__ void k_scan() {   // single CTA, 1024 threads, 4 elems each
    __shared__ int ssum[1024];
    int t = threadIdx.x;
    int base = t * 4;
    int c0 = g_cnt[base], c1 = g_cnt[base + 1],
        c2 = g_cnt[base + 2], c3 = g_cnt[base + 3];
    int s = c0 + c1 + c2 + c3;
    ssum[t] = s;
    __syncthreads();
    for (int off = 1; off < 1024; off <<= 1) {
        int v = (t >= off) ? ssum[t - off] : 0;
        __syncthreads();
        ssum[t] += v;
        __syncthreads();
    }
    int excl = ssum[t] - s;
    g_off[base]     = excl;
    g_off[base + 1] = excl + c0;
    g_off[base + 2] = excl + c0 + c1;
    g_off[base + 3] = excl + c0 + c1 + c2;
    if (t == 1023) g_off[Nn] = ssum[1023];
}

__global__ void k_scatter(const int* __restrict__ esnk) {
    int e = blockIdx.x * blockDim.x + threadIdx.x;
    if (e < Ee) {
        int s = esnk[e];
        int p = atomicAdd(&g_pos[s], 1);
        g_eid[g_off[s] + p] = e;
    }
}

// ---------------------------------------------------------------------------
// GEMM framework: 256 threads = 8 warps; block tile 128x128, K-step 16,
// 2-stage cp.async; warp tile 64x32 = 4x4 m16n8k8.

#define GEMM_PROLOG                                                      \
    const int tid  = threadIdx.x;                                        \
    const int lane = tid & 31;                                           \
    const int warp = tid >> 5;                                           \
    const int grp  = lane >> 2;                                          \
    const int tig  = lane & 3;                                           \
    const int wM   = (warp & 1) * 64;                                    \
    const int wN   = (warp >> 1) * 32;                                   \
    const int ar   = tid >> 1;                                           \
    const int akq  = (tid & 1) * 8;                                      \
    const int bkr  = tid >> 4;                                           \
    const int bnq  = (tid & 15) * 8;                                     \
    const int lrow = lane & 15;                                          \
    const int lcol = (lane >> 4) * 4;                                    \
    const uint32_t sA = (uint32_t)__cvta_generic_to_shared(&As[0][0][0]);\
    const uint32_t sB = (uint32_t)__cvta_generic_to_shared(&Bs[0][0][0]);\
    float acc[4][4][4];                                                  \
    _Pragma("unroll") for (int i = 0; i < 4; i++)                        \
    _Pragma("unroll") for (int j = 0; j < 4; j++)                        \
    _Pragma("unroll") for (int q = 0; q < 4; q++) acc[i][j][q] = 0.f;

#define A_ADDR(st, m, k) (sA + (((st) * 128 + (m)) * SKA + (k)) * 4u)
#define B_ADDR(st, k, n) (sB + (((st) * 16  + (k)) * SKB + (n)) * 4u)

#define COMPUTE(st)                                                      \
    _Pragma("unroll") for (int kb = 0; kb < 16; kb += 8) {               \
        uint32_t af[4][4], bf[4][2];                                     \
        _Pragma("unroll") for (int mt = 0; mt < 4; mt++)                 \
            ldsm4(af[mt][0], af[mt][1], af[mt][2], af[mt][3],            \
                  A_ADDR(st, wM + mt * 16 + lrow, kb + lcol));           \
        _Pragma("unroll") for (int nt = 0; nt < 4; nt++) {               \
            int cc = wN + nt * 8 + grp;                                  \
            bf[nt][0] = Bs[st][kb + tig][cc];                            \
            bf[nt][1] = Bs[st][kb + tig + 4][cc];                        \
        }                                                                \
        _Pragma("unroll") for (int mt = 0; mt < 4; mt++)                 \
        _Pragma("unroll") for (int nt = 0; nt < 4; nt++)                 \
            mma8(acc[mt][nt], af[mt][0], af[mt][1], af[mt][2],           \
                 af[mt][3], bf[nt][0], bf[nt][1]);                       \
    }

#define PIPELINE(NITER, LOADER)                                          \
    LOADER(0, 0);                                                        \
    CP_COMMIT;                                                           \
    for (int it = 0; it < (NITER); it++) {                               \
        if (it + 1 < (NITER)) {                                          \
            LOADER((it + 1) & 1, (it + 1) * 16);                         \
            CP_COMMIT;                                                   \
            CP_WAIT1;                                                    \
        } else {                                                         \
            CP_WAIT0;                                                    \
        }                                                                \
        __syncthreads();                                                 \
        COMPUTE(it & 1);                                                 \
        __syncthreads();                                                 \
    }

#define SMEM_TILES                                                       \
    __shared__ uint32_t As[2][128][SKA];                                 \
    __shared__ uint32_t Bs[2][16][SKB];

// ---------------------------------------------------------------------------
// Node-projection GEMM: g_p = g_nsr @ g_We1c
// M = 32768, N = 1024, K = 256
__global__ __launch_bounds__(256, 2)
void k_pre()
{
    SMEM_TILES;
    GEMM_PROLOG;

    const int rowBase = blockIdx.y * 128;
    const int colBase = blockIdx.x * 128;

#define LOAD_P(st, k0)                                                   \
    {                                                                    \
        _Pragma("unroll") for (int q = 0; q < 2; q++)                    \
            cpa16(A_ADDR(st, ar, akq + q * 4),                           \
                  g_nsr + (size_t)(rowBase + ar) * Dd + (k0) + akq + q * 4); \
        _Pragma("unroll") for (int q = 0; q < 2; q++)                    \
            cpa16(B_ADDR(st, bkr, bnq + q * 4),                          \
                  g_We1c + (size_t)((k0) + bkr) * 1024 + colBase + bnq + q * 4); \
    }

    PIPELINE(16, LOAD_P);

#pragma unroll
    for (int mt = 0; mt < 4; mt++) {
        int r0 = rowBase + wM + mt * 16 + grp;
#pragma unroll
        for (int nt = 0; nt < 4; nt++) {
            int c0 = colBase + wN + nt * 8 + tig * 2;
            float* a = acc[mt][nt];
            *(float2*)(g_p + (size_t)r0 * 1024 + c0)       = make_float2(a[0], a[1]);
            *(float2*)(g_p + (size_t)(r0 + 8) * 1024 + c0) = make_float2(a[2], a[3]);
        }
    }
}

// ---------------------------------------------------------------------------
// Fused edge MLP: h = rna(relu(P[src]+P[snk]+be1)); msgs = h @ We2r + be2
// Stored densely to g_msg (gathered later via CSR).
// M = B*E = 131072, N = 256, K = 512
__global__ __launch_bounds__(256, 2)
void k_edge2f(const float* __restrict__ be1, const float* __restrict__ be2,
              const int* __restrict__ esrc, const int* __restrict__ esnk)
{
    SMEM_TILES;
    __shared__ int sIdx[2][128];

    GEMM_PROLOG;

    const int rowBase = blockIdx.y * 128;
    const int colBase = blockIdx.x * 128;
    const int b  = rowBase >> 14;
    const int e0 = rowBase & (Ee - 1);

    if (tid < 128)      sIdx[0][tid]       = esrc[e0 + tid];
    else                sIdx[1][tid - 128] = esnk[e0 + tid - 128];
    __syncthreads();

    const float* Pb = g_p + (size_t)b * Nn * 1024;
    const size_t srcRow = (size_t)sIdx[0][ar] * 1024;
    const size_t snkRow = (size_t)sIdx[1][ar] * 1024 + 512;

    float4 u0, u1, v0, v1;

#define ISSUE_EF(k0)                                                     \
    {                                                                    \
        u0 = *(const float4*)(Pb + srcRow + (k0) + akq);                 \
        u1 = *(const float4*)(Pb + srcRow + (k0) + akq + 4);             \
        v0 = *(const float4*)(Pb + snkRow + (k0) + akq);                 \
        v1 = *(const float4*)(Pb + snkRow + (k0) + akq + 4);             \
    }

#define COMMIT_EF(st, k0)                                                \
    {                                                                    \
        float4 b0 = *(const float4*)(be1 + (k0) + akq);                  \
        float4 b1 = *(const float4*)(be1 + (k0) + akq + 4);              \
        uint32_t* dst = (uint32_t*)&As[st][ar][akq];                     \
        dst[0] = f2tf(fmaxf(u0.x + v0.x + b0.x, 0.f));                   \
        dst[1] = f2tf(fmaxf(u0.y + v0.y + b0.y, 0.f));                   \
        dst[2] = f2tf(fmaxf(u0.z + v0.z + b0.z, 0.f));                   \
        dst[3] = f2tf(fmaxf(u0.w + v0.w + b0.w, 0.f));                   \
        dst[4] = f2tf(fmaxf(u1.x + v1.x + b1.x, 0.f));                   \
        dst[5] = f2tf(fmaxf(u1.y + v1.y + b1.y, 0.f));                   \
        dst[6] = f2tf(fmaxf(u1.z + v1.z + b1.z, 0.f));                   \
        dst[7] = f2tf(fmaxf(u1.w + v1.w + b1.w, 0.f));                   \
    }

#define LOADB_EF(st, k0)                                                 \
    _Pragma("unroll") for (int q = 0; q < 2; q++)                        \
        cpa16(B_ADDR(st, bkr, bnq + q * 4),                              \
              g_We2r + (size_t)((k0) + bkr) * MSGm + colBase + bnq + q * 4);

    ISSUE_EF(0);
    LOADB_EF(0, 0);
    CP_COMMIT;
    COMMIT_EF(0, 0);

    for (int it = 0; it < 32; it++) {
        if (it + 1 < 32) {
            ISSUE_EF((it + 1) * 16);
            LOADB_EF((it + 1) & 1, (it + 1) * 16);
            CP_COMMIT;
            CP_WAIT1;
        } else {
            CP_WAIT0;
        }
        __syncthreads();
        COMPUTE(it & 1);
        if (it + 1 < 32) COMMIT_EF((it + 1) & 1, (it + 1) * 16);
        __syncthreads();
    }

#pragma unroll
    for (int mt = 0; mt < 4; mt++) {
        int r0 = rowBase + wM + mt * 16 + grp;
#pragma unroll
        for (int nt = 0; nt < 4; nt++) {
            int c0 = colBase + wN + nt * 8 + tig * 2;
            float b0 = be2[c0], b1 = be2[c0 + 1];
            float* a = acc[mt][nt];
            *(float2*)(g_msg + (size_t)r0 * MSGm + c0) =
                make_float2(a[0] + b0, a[1] + b1);
            *(float2*)(g_msg + (size_t)(r0 + 8) * MSGm + c0) =
                make_float2(a[2] + b0, a[3] + b1);
        }
    }
}

// ---------------------------------------------------------------------------
// CSR gather: g_inc[b,n,:] = rna(sum over edges e with snk[e]==n of g_msg[b,e,:])
// One warp per (b, node); lanes cover 256 cols as 2 float4s.
__global__ __launch_bounds__(256)
void k_gather()
{
    const int wid  = threadIdx.x >> 5;
    const int lane = threadIdx.x & 31;
    const int n = blockIdx.x * 8 + wid;
    const int b = blockIdx.y;

    const int o0 = g_off[n], o1 = g_off[n + 1];
    const float* msgb = g_msg + (size_t)b * Ee * MSGm;

    float4 a0 = make_float4(0.f, 0.f, 0.f, 0.f);
    float4 a1 = make_float4(0.f, 0.f, 0.f, 0.f);

    for (int j = o0; j < o1; j++) {
        const float* r = msgb + (size_t)g_eid[j] * MSGm;
        float4 u = *(const float4*)(r + lane * 4);
        float4 v = *(const float4*)(r + 128 + lane * 4);
        a0.x += u.x; a0.y += u.y; a0.z += u.z; a0.w += u.w;
        a1.x += v.x; a1.y += v.y; a1.z += v.z; a1.w += v.w;
    }

    float* dst = g_inc + ((size_t)b * Nn + n) * MSGm;
    *(float4*)(dst + lane * 4) =
        make_float4(rndf(a0.x), rndf(a0.y), rndf(a0.z), rndf(a0.w));
    *(float4*)(dst + 128 + lane * 4) =
        make_float4(rndf(a1.x), rndf(a1.y), rndf(a1.z), rndf(a1.w));
}

// ---------------------------------------------------------------------------
// Node MLP layer 1: g_h2 = rna(relu(concat(g_inc, g_nsr) @ Wn1r + b_n1))
// M = 32768, N = 512, K = 512
__global__ __launch_bounds__(256, 2)
void k_node1(const float* __restrict__ bn1)
{
    SMEM_TILES;
    GEMM_PROLOG;

    const int rowBase = blockIdx.y * 128;
    const int colBase = blockIdx.x * 128;

#define LOAD_N1(st, k0)                                                  \
    {                                                                    \
        _Pragma("unroll") for (int q = 0; q < 2; q++) {                  \
            int kg = (k0) + akq + q * 4;                                 \
            const float* src = (kg < MSGm)                               \
                ? (g_inc + (size_t)(rowBase + ar) * MSGm + kg)           \
                : (g_nsr + (size_t)(rowBase + ar) * Dd + (kg - MSGm));   \
            cpa16(A_ADDR(st, ar, akq + q * 4), src);                     \
        }                                                                \
        _Pragma("unroll") for (int q = 0; q < 2; q++)                    \
            cpa16(B_ADDR(st, bkr, bnq + q * 4),                          \
                  g_Wn1r + (size_t)((k0) + bkr) * Hh + colBase + bnq + q * 4); \
    }

    PIPELINE(32, LOAD_N1);

#pragma unroll
    for (int mt = 0; mt < 4; mt++) {
        int r0 = rowBase + wM + mt * 16 + grp;
#pragma unroll
        for (int nt = 0; nt < 4; nt++) {
            int c0 = colBase + wN + nt * 8 + tig * 2;
            float b0 = bn1[c0], b1 = bn1[c0 + 1];
            float* a = acc[mt][nt];
            *(float2*)(g_h2 + (size_t)r0 * Hh + c0) =
                make_float2(rndf(fmaxf(a[0] + b0, 0.f)), rndf(fmaxf(a[1] + b1, 0.f)));
            *(float2*)(g_h2 + (size_t)(r0 + 8) * Hh + c0) =
                make_float2(rndf(fmaxf(a[2] + b0, 0.f)), rndf(fmaxf(a[3] + b1, 0.f)));
        }
    }
}

// ---------------------------------------------------------------------------
// Node MLP layer 2 + in-place update
// M = 32768, N = 254 (padded 256), K = 512
__global__ __launch_bounds__(256, 2)
void k_node2(const float* __restrict__ bn2)
{
    SMEM_TILES;
    GEMM_PROLOG;

    const int rowBase = blockIdx.y * 128;
    const int colBase = blockIdx.x * 128;

    const float* Ag = g_h2 + (size_t)rowBase * Hh;

#define LOAD_N2(st, k0)                                                  \
    {                                                                    \
        _Pragma("unroll") for (int q = 0; q < 2; q++)                    \
            cpa16(A_ADDR(st, ar, akq + q * 4),                           \
                  Ag + (size_t)ar * Hh + (k0) + akq + q * 4);            \
        _Pragma("unroll") for (int q = 0; q < 2; q++)                    \
            cpa16(B_ADDR(st, bkr, bnq + q * 4),                          \
                  g_Wn2r + (size_t)((k0) + bkr) * 256 + colBase + bnq + q * 4); \
    }

    PIPELINE(32, LOAD_N2);

#pragma unroll
    for (int mt = 0; mt < 4; mt++) {
        int r0 = rowBase + wM + mt * 16 + grp;
#pragma unroll
        for (int nt = 0; nt < 4; nt++) {
            int c0 = colBase + wN + nt * 8 + tig * 2;
            float* a = acc[mt][nt];
#pragma unroll
            for (int h = 0; h < 2; h++) {
                int c = c0 + h;
                if (c < UPDu) {
                    float bb = bn2[c];
                    size_t i0 = (size_t)r0 * Dd + 2 + c;
                    size_t i1 = (size_t)(r0 + 8) * Dd + 2 + c;
                    float v0 = g_ns[i0] + a[h]     + bb;
                    float v1 = g_ns[i1] + a[2 + h] + bb;
                    g_ns[i0] = v0;  g_nsr[i0] = rndf(v0);
                    g_ns[i1] = v1;  g_nsr[i1] = rndf(v1);
                }
            }
        }
    }
}

// ---------------------------------------------------------------------------
// Extraction: out[b,p,d] = sum_n attn[b,p,n] * ns[b,n,d]; 8 p's per CTA.
__global__ __launch_bounds__(256)
void k_extract(const float* __restrict__ attn, float* __restrict__ out)
{
    const int pg = blockIdx.x;   // p group: p = pg*8 .. pg*8+7
    const int b  = blockIdx.y;
    const int d  = threadIdx.x;

    const float* nsb = g_ns + (size_t)b * Nn * Dd;

    __shared__ float sa[8][256];
    float acc[8];
#pragma unroll
    for (int pp = 0; pp < 8; pp++) acc[pp] = 0.f;

    for (int n0 = 0; n0 < Nn; n0 += 256) {
        __syncthreads();
#pragma unroll
        for (int pp = 0; pp < 8; pp++)
            sa[pp][d] = attn[((size_t)b * Pp + pg * 8 + pp) * Nn + n0 + d];
        __syncthreads();
#pragma unroll 4
        for (int n = 0; n < 256; n++) {
            float x = nsb[(size_t)(n0 + n) * Dd + d];
#pragma unroll
            for (int pp = 0; pp < 8; pp++)
                acc[pp] = fmaf(sa[pp][n], x, acc[pp]);
        }
    }

#pragma unroll
    for (int pp = 0; pp < 8; pp++)
        out[((size_t)b * Pp + pg * 8 + pp) * Dd + d] = acc[pp];
}

// ---------------------------------------------------------------------------
extern "C" void kernel_launch(void* const* d_in, const int* in_sizes, int n_in,
                              void* d_out, int out_size)
{
    const float* nodes = (const float*)d_in[0];
    const float* attn  = (const float*)d_in[1];
    const float* We1   = (const float*)d_in[2];
    const float* be1   = (const float*)d_in[3];
    const float* We2   = (const float*)d_in[4];
    const float* be2   = (const float*)d_in[5];
    const float* Wn1   = (const float*)d_in[6];
    const float* bn1   = (const float*)d_in[7];
    const float* Wn2   = (const float*)d_in[8];
    const float* bn2   = (const float*)d_in[9];
    const int*   esrc  = (const int*)d_in[10];
    const int*   esnk  = (const int*)d_in[11];
    float* out = (float*)d_out;

    float* dWe2r; cudaGetSymbolAddress((void**)&dWe2r, g_We2r);
    float* dWn1r; cudaGetSymbolAddress((void**)&dWn1r, g_Wn1r);

    // Prologue: weights + state copies + CSR of edge_sinks
    k_make_we1c<<<(Dd * 1024 + 255) / 256, 256>>>(We1);
    k_round<<<(Hh * MSGm + 255) / 256, 256>>>(We2, dWe2r, Hh * MSGm);
    k_round<<<((Dd + MSGm) * Hh + 255) / 256, 256>>>(Wn1, dWn1r, (Dd + MSGm) * Hh);
    k_round_pad_wn2<<<(Hh * 256 + 255) / 256, 256>>>(Wn2);
    k_copy_ns<<<(Bb * Nn * Dd + 255) / 256, 256>>>(nodes);
    k_zero_csr<<<(Nn + 255) / 256, 256>>>();
    k_hist<<<(Ee + 255) / 256, 256>>>(esnk);
    k_scan<<<1, 1024>>>();
    k_scatter<<<(Ee + 255) / 256, 256>>>(esnk);

    for (int s = 0; s < STEPS; s++) {
        k_pre<<<dim3(1024 / 128, (Bb * Nn) / 128), 256>>>();
        k_edge2f<<<dim3(MSGm / 128, (Bb * Ee) / 128), 256>>>(be1, be2, esrc, esnk);
        k_gather<<<dim3(Nn / 8, Bb), 256>>>();
        k_node1<<<dim3(Hh / 128, (Bb * Nn) / 128), 256>>>(bn1);
        k_node2<<<dim3(2, (Bb * Nn) / 128), 256>>>(bn2);
    }

    k_extract<<<dim3(Pp / 8, Bb), 256>>>(attn, out);
}